// round 5
// baseline (speedup 1.0000x reference)
#include <cuda_runtime.h>

// Problem constants
#define BSZ     256
#define IDIM    182
#define IHALF   91           // 91 = 7*13, unroll 7 still exact
#define TSTEPS  2000
#define OCH     2
#define CHUNK   8            // steps per thread in scan phase
#define GRID    592          // 148 SMs * 4 CTAs -- exact occupancy shape
#define NUNITS  1000         // 500 column-blocks * 2 i-halves
#define HALF_OFF ((size_t)BSZ * OCH * TSTEPS)   // float offset between halves

// 8 MB scratch: two half-sums of per-step currents, layout [h][b][o][t]
__device__ float g_curr[2 * (size_t)BSZ * OCH * TSTEPS];

// work-stealing ticket + software grid barrier (generation counter; replay-safe)
__device__ unsigned g_ticket = 0;
__device__ unsigned g_bar_count = 0;
__device__ volatile unsigned g_bar_phase = 0;

// ---------------------------------------------------------------------------
// Fused persistent kernel, SM-balanced GEMM via global work-stealing.
//  phase 1 (592 CTAs): units u in [0,1000): column-block cb = u%500, half h = u/500
//     partial_curr[h][b][o][t] = sum_{i in half h} inp[b,i,t] * W[o,i]
//  grid barrier (releaser also resets the ticket -- all CTAs past work loop)
//  phase 2 (CTAs 0..255): log-depth chunked scan; curr = half0 + half1 + bias
// __launch_bounds__(256,4): 64 regs -> 4 CTAs/SM -> all 592 co-resident.
// ---------------------------------------------------------------------------
__global__ __launch_bounds__(256, 4)
void snn_fused_kernel(const float* __restrict__ inp,   // [B, I, T]
                      const float* __restrict__ W,     // [O, I]
                      const float* __restrict__ bias,  // [O]
                      const float* __restrict__ alpha,
                      const float* __restrict__ beta,
                      float* __restrict__ out)         // [B, T, O]
{
    __shared__ float Wsh[OCH][IDIM];
    __shared__ int   s_u;
    __shared__ float Ts[OCH][8][2];   // warp totals (syn, mem)
    __shared__ float Es[OCH][8][2];   // warp exclusive prefixes

    const int tid = threadIdx.x;

    for (int k = tid; k < OCH * IDIM; k += 256)
        Wsh[k / IDIM][k % IDIM] = W[k];
    __syncthreads();

    // ======================= phase 1: GEMM (work-stealing) =======================
    while (true) {
        if (tid == 0)
            s_u = (int)atomicAdd(&g_ticket, 1u);
        __syncthreads();
        const int u = s_u;
        if (u >= NUNITS) break;

        const int cb = u % 500;          // column block
        const int h  = u / 500;          // i-half
        const int g  = cb * 256 + tid;   // global column id 0..127999
        const int bb = g / 500;
        const int c  = g % 500;
        const int t0 = c * 4;

        const float* ib = inp + ((size_t)bb * IDIM + h * IHALF) * TSTEPS + t0;
        const float* wr0 = &Wsh[0][h * IHALF];
        const float* wr1 = &Wsh[1][h * IHALF];

        float4 acc0 = make_float4(0.f, 0.f, 0.f, 0.f);
        float4 acc1 = make_float4(0.f, 0.f, 0.f, 0.f);

        #pragma unroll 7
        for (int i = 0; i < IHALF; i++) {
            const float4 x = __ldcs(reinterpret_cast<const float4*>(ib + (size_t)i * TSTEPS));
            const float w0 = wr0[i];
            const float w1 = wr1[i];
            acc0.x = fmaf(w0, x.x, acc0.x); acc0.y = fmaf(w0, x.y, acc0.y);
            acc0.z = fmaf(w0, x.z, acc0.z); acc0.w = fmaf(w0, x.w, acc0.w);
            acc1.x = fmaf(w1, x.x, acc1.x); acc1.y = fmaf(w1, x.y, acc1.y);
            acc1.z = fmaf(w1, x.z, acc1.z); acc1.w = fmaf(w1, x.w, acc1.w);
        }

        float* dst0 = g_curr + (size_t)h * HALF_OFF + ((size_t)bb * OCH + 0) * TSTEPS + t0;
        float* dst1 = g_curr + (size_t)h * HALF_OFF + ((size_t)bb * OCH + 1) * TSTEPS + t0;
        *reinterpret_cast<float4*>(dst0) = acc0;
        *reinterpret_cast<float4*>(dst1) = acc1;

        __syncthreads();   // protect s_u before next grab
    }

    // ======================= grid barrier =======================
    const unsigned gen = g_bar_phase;   // volatile read, before arrival
    __syncthreads();                    // all threads hold gen
    __threadfence();                    // g_curr writes visible device-wide
    if (tid == 0) {
        const unsigned prev = atomicAdd(&g_bar_count, 1);
        if (prev == GRID - 1) {
            g_bar_count = 0;            // reset for next graph replay
            g_ticket    = 0;            // safe: every CTA is past the work loop
            __threadfence();
            g_bar_phase = gen + 1;      // release
        }
    }
    if (blockIdx.x >= BSZ) return;      // non-scan blocks leave after arriving

    if (tid == 0) {
        while (g_bar_phase == gen) { /* spin */ }
    }
    __syncthreads();
    __threadfence();                    // acquire: see all g_curr writes

    // ======================= phase 2: scan =======================
    const int j    = tid;               // chunk index 0..255
    const int lane = j & 31;
    const int w    = j >> 5;
    const int b    = blockIdx.x;
    const int t0   = j * CHUNK;
    const bool live = (t0 < TSTEPS);    // 2000 = 8*250

    float a[OCH], m[OCH], bo[OCH];
    a[0]  = __saturatef(alpha[0]); a[1]  = __saturatef(alpha[1]);
    m[0]  = __saturatef(beta[0]);  m[1]  = __saturatef(beta[1]);
    bo[0] = bias[0];               bo[1] = bias[1];

    // phase A: load both half-currents, sum + bias, local scan from zero state
    float c[OCH][CHUNK];
    float vs[OCH], vm[OCH];
    #pragma unroll
    for (int o = 0; o < OCH; o++) {
        const float* srcA = g_curr + ((size_t)b * OCH + o) * TSTEPS + t0;
        const float* srcB = srcA + HALF_OFF;
        float4 xa0 = make_float4(0.f,0.f,0.f,0.f), xa1 = xa0, xb0 = xa0, xb1 = xa0;
        if (live) {
            xa0 = *reinterpret_cast<const float4*>(srcA);
            xa1 = *reinterpret_cast<const float4*>(srcA + 4);
            xb0 = *reinterpret_cast<const float4*>(srcB);
            xb1 = *reinterpret_cast<const float4*>(srcB + 4);
        }
        const float bb = live ? bo[o] : 0.f;
        c[o][0] = xa0.x + xb0.x + bb; c[o][1] = xa0.y + xb0.y + bb;
        c[o][2] = xa0.z + xb0.z + bb; c[o][3] = xa0.w + xb0.w + bb;
        c[o][4] = xa1.x + xb1.x + bb; c[o][5] = xa1.y + xb1.y + bb;
        c[o][6] = xa1.z + xb1.z + bb; c[o][7] = xa1.w + xb1.w + bb;
        float s = 0.f, q = 0.f;
        #pragma unroll
        for (int k = 0; k < CHUNK; k++) {
            s = fmaf(a[o], s, c[o][k]);
            q = fmaf(m[o], q, s);
        }
        vs[o] = s; vm[o] = q;
    }

    // P = M^CHUNK per channel:  M = [[a,0],[a,m]], M^k = [[A,0],[C,B]]
    float PA[OCH], PB[OCH], PC[OCH];
    #pragma unroll
    for (int o = 0; o < OCH; o++) {
        float A = 1.f, B = 1.f, C = 0.f;
        #pragma unroll
        for (int k = 0; k < CHUNK; k++) {
            A = a[o] * A;
            C = fmaf(m[o], C, A);
            B = m[o] * B;
        }
        PA[o] = A; PB[o] = B; PC[o] = C;
    }

    // phase B: Kogge-Stone intra-warp scan; build L = P^lane on the fly
    float LA[OCH] = {1.f, 1.f}, LB[OCH] = {1.f, 1.f}, LC[OCH] = {0.f, 0.f};

    #pragma unroll
    for (int d = 1; d <= 16; d <<= 1) {
        #pragma unroll
        for (int o = 0; o < OCH; o++) {
            if (lane & d) {
                const float nA = LA[o] * PA[o];
                const float nB = LB[o] * PB[o];
                const float nC = fmaf(LC[o], PA[o], LB[o] * PC[o]);
                LA[o] = nA; LB[o] = nB; LC[o] = nC;
            }
        }
        #pragma unroll
        for (int o = 0; o < OCH; o++) {
            const float ws = __shfl_up_sync(0xffffffffu, vs[o], d);
            const float wq = __shfl_up_sync(0xffffffffu, vm[o], d);
            if (lane >= d) {
                vm[o] = fmaf(PC[o], ws, fmaf(PB[o], wq, vm[o]));
                vs[o] = fmaf(PA[o], ws, vs[o]);
            }
        }
        #pragma unroll
        for (int o = 0; o < OCH; o++) {
            PC[o] = PC[o] * (PA[o] + PB[o]);
            PA[o] = PA[o] * PA[o];
            PB[o] = PB[o] * PB[o];
        }
    }
    // P now holds P^32 (warp-span matrix)

    if (lane == 31) {
        #pragma unroll
        for (int o = 0; o < OCH; o++) {
            Ts[o][w][0] = vs[o];
            Ts[o][w][1] = vm[o];
        }
    }
    __syncthreads();

    if (j < OCH) {
        const int o = j;
        float Ss = 0.f, Sm = 0.f;
        #pragma unroll
        for (int k = 0; k < 8; k++) {
            Es[o][k][0] = Ss;
            Es[o][k][1] = Sm;
            const float ts = Ts[o][k][0];
            const float tm = Ts[o][k][1];
            const float ns = fmaf(PA[o], Ss, ts);
            const float nm = fmaf(PC[o], Ss, fmaf(PB[o], Sm, tm));
            Ss = ns; Sm = nm;
        }
    }
    __syncthreads();

    // phase C: chunk prefix = P^lane * E_w + intra-warp exclusive; replay & store
    if (live) {
        float2* ob = reinterpret_cast<float2*>(out) + (size_t)b * TSTEPS + t0;
        float pre_s[OCH], pre_m[OCH];
        #pragma unroll
        for (int o = 0; o < OCH; o++) {
            float Xs = __shfl_up_sync(0xffffffffu, vs[o], 1);
            float Xm = __shfl_up_sync(0xffffffffu, vm[o], 1);
            if (lane == 0) { Xs = 0.f; Xm = 0.f; }
            const float es = Es[o][w][0];
            const float em = Es[o][w][1];
            pre_s[o] = fmaf(LA[o], es, Xs);
            pre_m[o] = fmaf(LC[o], es, fmaf(LB[o], em, Xm));
        }
        float s0 = pre_s[0], q0 = pre_m[0];
        float s1 = pre_s[1], q1 = pre_m[1];
        #pragma unroll
        for (int k = 0; k < CHUNK; k++) {
            s0 = fmaf(a[0], s0, c[0][k]); q0 = fmaf(m[0], q0, s0);
            s1 = fmaf(a[1], s1, c[1][k]); q1 = fmaf(m[1], q1, s1);
            ob[k] = make_float2(q0, q1);
        }
    }
}

extern "C" void kernel_launch(void* const* d_in, const int* in_sizes, int n_in,
                              void* d_out, int out_size)
{
    const float* inp   = (const float*)d_in[0]; // [256,182,2000]
    const float* W     = (const float*)d_in[1]; // [2,182]
    const float* bias  = (const float*)d_in[2]; // [2]
    const float* alpha = (const float*)d_in[3]; // [2]
    const float* beta  = (const float*)d_in[4]; // [2]
    float* out = (float*)d_out;                 // [256,2000,2]

    snn_fused_kernel<<<GRID, 256>>>(inp, W, bias, alpha, beta, out);
}

// round 6
// speedup vs baseline: 1.0183x; 1.0183x over previous
#include <cuda_runtime.h>

// Problem constants
#define BSZ     256
#define IDIM    182
#define TSTEPS  2000
#define THALF   1000
#define OCH     2
#define CHUNK   8            // steps per thread in scan phase
#define GRID    (BSZ * 2)    // CTA 2b+h: batch b, t-half h

// 4 MB scratch for per-step currents (bias included), layout [b][o][t]
__device__ float g_curr[(size_t)BSZ * OCH * TSTEPS];

// per-batch arrival counters (zero-init; scanning CTA resets its own -> replay-safe)
__device__ unsigned g_ready[BSZ];

// ---------------------------------------------------------------------------
// Fused kernel, no grid barrier:
//   GEMM: CTA 2b+h computes curr[b][o][t] = <inp[b,:,t], W[o,:]> + bias[o]
//         for t in [h*1000, h*1000+1000)   (full I-reduction, 250 float4 cols)
//   then atomicAdd(ready[b]); the SECOND finisher runs the log-depth scan for
//   batch b inline, overlapped with other CTAs' GEMM work. Deadlock-free:
//   nothing ever spins.
// ---------------------------------------------------------------------------
__global__ __launch_bounds__(256, 4)
void snn_fused_kernel(const float* __restrict__ inp,   // [B, I, T]
                      const float* __restrict__ W,     // [O, I]
                      const float* __restrict__ bias,  // [O]
                      const float* __restrict__ alpha,
                      const float* __restrict__ beta,
                      float* __restrict__ out)         // [B, T, O]
{
    __shared__ float Wsh[OCH][IDIM];
    __shared__ int   s_last;
    __shared__ float Ts[OCH][8][2];   // warp totals (syn, mem)
    __shared__ float Es[OCH][8][2];   // warp exclusive prefixes

    const int tid = threadIdx.x;
    const int b   = blockIdx.x >> 1;
    const int h   = blockIdx.x & 1;

    for (int k = tid; k < OCH * IDIM; k += 256)
        Wsh[k / IDIM][k % IDIM] = W[k];
    __syncthreads();

    // ======================= phase 1: GEMM (this CTA's 250 columns) ===========
    if (tid < THALF / 4) {
        const int t0 = h * THALF + tid * 4;
        const float* ib = inp + (size_t)b * IDIM * TSTEPS + t0;

        float4 acc0 = make_float4(0.f, 0.f, 0.f, 0.f);
        float4 acc1 = make_float4(0.f, 0.f, 0.f, 0.f);

        #pragma unroll 7
        for (int i = 0; i < IDIM; i++) {
            const float4 x = __ldcs(reinterpret_cast<const float4*>(ib + (size_t)i * TSTEPS));
            const float w0 = Wsh[0][i];
            const float w1 = Wsh[1][i];
            acc0.x = fmaf(w0, x.x, acc0.x); acc0.y = fmaf(w0, x.y, acc0.y);
            acc0.z = fmaf(w0, x.z, acc0.z); acc0.w = fmaf(w0, x.w, acc0.w);
            acc1.x = fmaf(w1, x.x, acc1.x); acc1.y = fmaf(w1, x.y, acc1.y);
            acc1.z = fmaf(w1, x.z, acc1.z); acc1.w = fmaf(w1, x.w, acc1.w);
        }

        const float b0 = bias[0];
        const float b1 = bias[1];
        acc0.x += b0; acc0.y += b0; acc0.z += b0; acc0.w += b0;
        acc1.x += b1; acc1.y += b1; acc1.z += b1; acc1.w += b1;

        float* dst0 = g_curr + ((size_t)b * OCH + 0) * TSTEPS + t0;
        float* dst1 = g_curr + ((size_t)b * OCH + 1) * TSTEPS + t0;
        *reinterpret_cast<float4*>(dst0) = acc0;
        *reinterpret_cast<float4*>(dst1) = acc1;
    }

    // ======================= handoff: second finisher scans ===================
    __syncthreads();
    __threadfence();                    // publish this CTA's curr stores
    if (tid == 0) {
        const unsigned prev = atomicAdd(&g_ready[b], 1u);
        s_last = (prev == 1u);
        if (prev == 1u)
            g_ready[b] = 0;             // reset for next graph replay
    }
    __syncthreads();
    if (!s_last) return;                // first finisher leaves
    __threadfence();                    // acquire: see peer CTA's curr stores

    // ======================= phase 2: scan for batch b ========================
    const int j    = tid;               // chunk index 0..255
    const int lane = j & 31;
    const int w    = j >> 5;
    const int t0   = j * CHUNK;
    const bool live = (t0 < TSTEPS);    // 2000 = 8*250

    float a[OCH], m[OCH];
    a[0] = __saturatef(alpha[0]); a[1] = __saturatef(alpha[1]);
    m[0] = __saturatef(beta[0]);  m[1] = __saturatef(beta[1]);

    // phase A: load chunk currents, local scan from zero state
    float c[OCH][CHUNK];
    float vs[OCH], vm[OCH];
    #pragma unroll
    for (int o = 0; o < OCH; o++) {
        const float* src = g_curr + ((size_t)b * OCH + o) * TSTEPS + t0;
        float4 x0 = make_float4(0.f, 0.f, 0.f, 0.f);
        float4 x1 = make_float4(0.f, 0.f, 0.f, 0.f);
        if (live) {
            x0 = *reinterpret_cast<const float4*>(src);
            x1 = *reinterpret_cast<const float4*>(src + 4);
        }
        c[o][0] = x0.x; c[o][1] = x0.y; c[o][2] = x0.z; c[o][3] = x0.w;
        c[o][4] = x1.x; c[o][5] = x1.y; c[o][6] = x1.z; c[o][7] = x1.w;
        float s = 0.f, q = 0.f;
        #pragma unroll
        for (int k = 0; k < CHUNK; k++) {
            s = fmaf(a[o], s, c[o][k]);
            q = fmaf(m[o], q, s);
        }
        vs[o] = s; vm[o] = q;
    }

    // P = M^CHUNK per channel:  M = [[a,0],[a,m]], M^k = [[A,0],[C,B]]
    float PA[OCH], PB[OCH], PC[OCH];
    #pragma unroll
    for (int o = 0; o < OCH; o++) {
        float A = 1.f, B = 1.f, C = 0.f;
        #pragma unroll
        for (int k = 0; k < CHUNK; k++) {
            A = a[o] * A;
            C = fmaf(m[o], C, A);
            B = m[o] * B;
        }
        PA[o] = A; PB[o] = B; PC[o] = C;
    }

    // phase B: Kogge-Stone intra-warp scan; build L = P^lane on the fly
    float LA[OCH] = {1.f, 1.f}, LB[OCH] = {1.f, 1.f}, LC[OCH] = {0.f, 0.f};

    #pragma unroll
    for (int d = 1; d <= 16; d <<= 1) {
        #pragma unroll
        for (int o = 0; o < OCH; o++) {
            if (lane & d) {
                const float nA = LA[o] * PA[o];
                const float nB = LB[o] * PB[o];
                const float nC = fmaf(LC[o], PA[o], LB[o] * PC[o]);
                LA[o] = nA; LB[o] = nB; LC[o] = nC;
            }
        }
        #pragma unroll
        for (int o = 0; o < OCH; o++) {
            const float ws = __shfl_up_sync(0xffffffffu, vs[o], d);
            const float wq = __shfl_up_sync(0xffffffffu, vm[o], d);
            if (lane >= d) {
                vm[o] = fmaf(PC[o], ws, fmaf(PB[o], wq, vm[o]));
                vs[o] = fmaf(PA[o], ws, vs[o]);
            }
        }
        #pragma unroll
        for (int o = 0; o < OCH; o++) {
            PC[o] = PC[o] * (PA[o] + PB[o]);
            PA[o] = PA[o] * PA[o];
            PB[o] = PB[o] * PB[o];
        }
    }
    // P now holds P^32 (warp-span matrix)

    if (lane == 31) {
        #pragma unroll
        for (int o = 0; o < OCH; o++) {
            Ts[o][w][0] = vs[o];
            Ts[o][w][1] = vm[o];
        }
    }
    __syncthreads();

    if (j < OCH) {
        const int o = j;
        float Ss = 0.f, Sm = 0.f;
        #pragma unroll
        for (int k = 0; k < 8; k++) {
            Es[o][k][0] = Ss;
            Es[o][k][1] = Sm;
            const float ts = Ts[o][k][0];
            const float tm = Ts[o][k][1];
            const float ns = fmaf(PA[o], Ss, ts);
            const float nm = fmaf(PC[o], Ss, fmaf(PB[o], Sm, tm));
            Ss = ns; Sm = nm;
        }
    }
    __syncthreads();

    // phase C: chunk prefix = P^lane * E_w + intra-warp exclusive; replay & store
    if (live) {
        float2* ob = reinterpret_cast<float2*>(out) + (size_t)b * TSTEPS + t0;
        float pre_s[OCH], pre_m[OCH];
        #pragma unroll
        for (int o = 0; o < OCH; o++) {
            float Xs = __shfl_up_sync(0xffffffffu, vs[o], 1);
            float Xm = __shfl_up_sync(0xffffffffu, vm[o], 1);
            if (lane == 0) { Xs = 0.f; Xm = 0.f; }
            const float es = Es[o][w][0];
            const float em = Es[o][w][1];
            pre_s[o] = fmaf(LA[o], es, Xs);
            pre_m[o] = fmaf(LC[o], es, fmaf(LB[o], em, Xm));
        }
        float s0 = pre_s[0], q0 = pre_m[0];
        float s1 = pre_s[1], q1 = pre_m[1];
        #pragma unroll
        for (int k = 0; k < CHUNK; k++) {
            s0 = fmaf(a[0], s0, c[0][k]); q0 = fmaf(m[0], q0, s0);
            s1 = fmaf(a[1], s1, c[1][k]); q1 = fmaf(m[1], q1, s1);
            ob[k] = make_float2(q0, q1);
        }
    }
}

extern "C" void kernel_launch(void* const* d_in, const int* in_sizes, int n_in,
                              void* d_out, int out_size)
{
    const float* inp   = (const float*)d_in[0]; // [256,182,2000]
    const float* W     = (const float*)d_in[1]; // [2,182]
    const float* bias  = (const float*)d_in[2]; // [2]
    const float* alpha = (const float*)d_in[3]; // [2]
    const float* beta  = (const float*)d_in[4]; // [2]
    float* out = (float*)d_out;                 // [256,2000,2]

    snn_fused_kernel<<<GRID, 256>>>(inp, W, bias, alpha, beta, out);
}

// round 7
// speedup vs baseline: 1.0493x; 1.0304x over previous
#include <cuda_runtime.h>

// Problem constants
#define BSZ     256
#define IDIM    182
#define TSTEPS  2000
#define THALF   1000
#define OCH     2
#define CHUNK   4            // steps per thread in scan phase (half = 4*250)
#define NCH     250          // live chunks per half
#define GRID    (BSZ * 2)    // CTA 2b+h: batch b, t-half h

// boundary handoff: half-0 final state (syn0,mem0,syn1,mem1) + flag per batch
__device__ float g_state[BSZ][4];
__device__ volatile unsigned g_flag[BSZ];   // zero-init; consumer resets -> replay-safe

// ---------------------------------------------------------------------------
// Fully fused, zero-scratch kernel.
//   CTA (b,h): curr[o][t] for t in [h*1000,(h+1)*1000) computed into SMEM,
//   then chunked log-depth scan of
//     syn_t = a*syn_{t-1} + c_t ;  mem_t = m*mem_{t-1} + syn_t
//   Half 1 seeds its warp-composition with half 0's final state (affine scan:
//   seeding the exclusive prefix is exact). Half 0 publishes that state via
//   a per-batch flag; the brief consumer spin is safe because
//   __launch_bounds__(256,4) guarantees all 512 CTAs co-resident (148*4=592).
// ---------------------------------------------------------------------------
__global__ __launch_bounds__(256, 4)
void snn_fused_kernel(const float* __restrict__ inp,   // [B, I, T]
                      const float* __restrict__ W,     // [O, I]
                      const float* __restrict__ bias,  // [O]
                      const float* __restrict__ alpha,
                      const float* __restrict__ beta,
                      float* __restrict__ out)         // [B, T, O]
{
    __shared__ float  Wsh[OCH][IDIM];
    __shared__ float4 csh[OCH][256];    // slot j = currents for local t [4j,4j+4)
    __shared__ float  Ts[OCH][8][2];    // warp totals (syn, mem)
    __shared__ float  Es[OCH][8][2];    // warp exclusive prefixes
    __shared__ float  Bnd[4];           // boundary seed

    const int tid = threadIdx.x;
    const int b   = blockIdx.x >> 1;
    const int h   = blockIdx.x & 1;

    for (int k = tid; k < OCH * IDIM; k += 256)
        Wsh[k / IDIM][k % IDIM] = W[k];
    __syncthreads();

    // ======================= phase 1: GEMM into SMEM ==========================
    if (tid < NCH) {
        const int t0 = h * THALF + tid * 4;
        const float* ib = inp + (size_t)b * IDIM * TSTEPS + t0;

        float4 acc0 = make_float4(0.f, 0.f, 0.f, 0.f);
        float4 acc1 = make_float4(0.f, 0.f, 0.f, 0.f);

        #pragma unroll 7
        for (int i = 0; i < IDIM; i++) {
            const float4 x = __ldcs(reinterpret_cast<const float4*>(ib + (size_t)i * TSTEPS));
            const float w0 = Wsh[0][i];
            const float w1 = Wsh[1][i];
            acc0.x = fmaf(w0, x.x, acc0.x); acc0.y = fmaf(w0, x.y, acc0.y);
            acc0.z = fmaf(w0, x.z, acc0.z); acc0.w = fmaf(w0, x.w, acc0.w);
            acc1.x = fmaf(w1, x.x, acc1.x); acc1.y = fmaf(w1, x.y, acc1.y);
            acc1.z = fmaf(w1, x.z, acc1.z); acc1.w = fmaf(w1, x.w, acc1.w);
        }

        const float b0 = bias[0];
        const float b1 = bias[1];
        acc0.x += b0; acc0.y += b0; acc0.z += b0; acc0.w += b0;
        acc1.x += b1; acc1.y += b1; acc1.z += b1; acc1.w += b1;

        csh[0][tid] = acc0;
        csh[1][tid] = acc1;
    } else {
        const float4 z = make_float4(0.f, 0.f, 0.f, 0.f);
        csh[0][tid] = z;
        csh[1][tid] = z;
    }
    __syncthreads();

    // ======================= phase 2: scan of this half ======================
    const int j    = tid;               // chunk index 0..255
    const int lane = j & 31;
    const int w    = j >> 5;
    const bool live = (j < NCH);

    float a[OCH], m[OCH];
    a[0] = __saturatef(alpha[0]); a[1] = __saturatef(alpha[1]);
    m[0] = __saturatef(beta[0]);  m[1] = __saturatef(beta[1]);

    // phase A: chunk currents from SMEM, local scan from zero state
    float c[OCH][CHUNK];
    float vs[OCH], vm[OCH];
    #pragma unroll
    for (int o = 0; o < OCH; o++) {
        const float4 x = csh[o][j];
        c[o][0] = x.x; c[o][1] = x.y; c[o][2] = x.z; c[o][3] = x.w;
        float s = 0.f, q = 0.f;
        #pragma unroll
        for (int k = 0; k < CHUNK; k++) {
            s = fmaf(a[o], s, c[o][k]);
            q = fmaf(m[o], q, s);
        }
        vs[o] = s; vm[o] = q;
    }

    // P = M^CHUNK per channel:  M = [[a,0],[a,m]], M^k = [[A,0],[C,B]]
    float PA[OCH], PB[OCH], PC[OCH];
    #pragma unroll
    for (int o = 0; o < OCH; o++) {
        float A = 1.f, B = 1.f, C = 0.f;
        #pragma unroll
        for (int k = 0; k < CHUNK; k++) {
            A = a[o] * A;
            C = fmaf(m[o], C, A);
            B = m[o] * B;
        }
        PA[o] = A; PB[o] = B; PC[o] = C;
    }

    // phase B: Kogge-Stone intra-warp scan; build L = P^lane on the fly
    float LA[OCH] = {1.f, 1.f}, LB[OCH] = {1.f, 1.f}, LC[OCH] = {0.f, 0.f};

    #pragma unroll
    for (int d = 1; d <= 16; d <<= 1) {
        #pragma unroll
        for (int o = 0; o < OCH; o++) {
            if (lane & d) {
                const float nA = LA[o] * PA[o];
                const float nB = LB[o] * PB[o];
                const float nC = fmaf(LC[o], PA[o], LB[o] * PC[o]);
                LA[o] = nA; LB[o] = nB; LC[o] = nC;
            }
        }
        #pragma unroll
        for (int o = 0; o < OCH; o++) {
            const float ws = __shfl_up_sync(0xffffffffu, vs[o], d);
            const float wq = __shfl_up_sync(0xffffffffu, vm[o], d);
            if (lane >= d) {
                vm[o] = fmaf(PC[o], ws, fmaf(PB[o], wq, vm[o]));
                vs[o] = fmaf(PA[o], ws, vs[o]);
            }
        }
        #pragma unroll
        for (int o = 0; o < OCH; o++) {
            PC[o] = PC[o] * (PA[o] + PB[o]);
            PA[o] = PA[o] * PA[o];
            PB[o] = PB[o] * PB[o];
        }
    }
    // P now holds P^32 (warp-span matrix)

    if (lane == 31) {
        #pragma unroll
        for (int o = 0; o < OCH; o++) {
            Ts[o][w][0] = vs[o];
            Ts[o][w][1] = vm[o];
        }
    }

    // boundary seed: half 0 -> zeros; half 1 -> wait for half 0's final state
    if (tid == 0) {
        if (h == 1) {
            while (g_flag[b] == 0u) { /* brief spin; producer co-resident */ }
            __threadfence();            // acquire: order state reads after flag
            Bnd[0] = g_state[b][0];
            Bnd[1] = g_state[b][1];
            Bnd[2] = g_state[b][2];
            Bnd[3] = g_state[b][3];
            g_flag[b] = 0u;             // consume: reset for next graph replay
        } else {
            Bnd[0] = 0.f; Bnd[1] = 0.f; Bnd[2] = 0.f; Bnd[3] = 0.f;
        }
    }
    __syncthreads();

    // serial composition over 8 warp totals, seeded with boundary state
    if (j < OCH) {
        const int o = j;
        float Ss = Bnd[2 * o + 0];
        float Sm = Bnd[2 * o + 1];
        #pragma unroll
        for (int k = 0; k < 8; k++) {
            Es[o][k][0] = Ss;
            Es[o][k][1] = Sm;
            const float ts = Ts[o][k][0];
            const float tm = Ts[o][k][1];
            const float ns = fmaf(PA[o], Ss, ts);
            const float nm = fmaf(PC[o], Ss, fmaf(PB[o], Sm, tm));
            Ss = ns; Sm = nm;
        }
    }
    __syncthreads();

    // phase C: chunk prefix = P^lane * E_w + intra-warp exclusive; replay & store
    if (live) {
        float pre_s[OCH], pre_m[OCH];
        #pragma unroll
        for (int o = 0; o < OCH; o++) {
            float Xs = __shfl_up_sync(0xffffffffu, vs[o], 1);
            float Xm = __shfl_up_sync(0xffffffffu, vm[o], 1);
            if (lane == 0) { Xs = 0.f; Xm = 0.f; }
            const float es = Es[o][w][0];
            const float em = Es[o][w][1];
            pre_s[o] = fmaf(LA[o], es, Xs);
            pre_m[o] = fmaf(LC[o], es, fmaf(LB[o], em, Xm));
        }
        float s0 = pre_s[0], q0 = pre_m[0];
        float s1 = pre_s[1], q1 = pre_m[1];

        float r[2 * CHUNK];
        #pragma unroll
        for (int k = 0; k < CHUNK; k++) {
            s0 = fmaf(a[0], s0, c[0][k]); q0 = fmaf(m[0], q0, s0);
            s1 = fmaf(a[1], s1, c[1][k]); q1 = fmaf(m[1], q1, s1);
            r[2 * k + 0] = q0;
            r[2 * k + 1] = q1;
        }

        // out[b][t][o], t = h*1000 + j*4 : 8 floats = two float4 streaming stores
        float4* ob = reinterpret_cast<float4*>(out + ((size_t)b * TSTEPS + h * THALF + j * 4) * OCH);
        __stcs(ob + 0, make_float4(r[0], r[1], r[2], r[3]));
        __stcs(ob + 1, make_float4(r[4], r[5], r[6], r[7]));

        // half 0's last chunk publishes the boundary state for half 1
        if (h == 0 && j == NCH - 1) {
            g_state[b][0] = s0;
            g_state[b][1] = q0;
            g_state[b][2] = s1;
            g_state[b][3] = q1;
            __threadfence();            // release: state before flag
            g_flag[b] = 1u;
        }
    }
}

extern "C" void kernel_launch(void* const* d_in, const int* in_sizes, int n_in,
                              void* d_out, int out_size)
{
    const float* inp   = (const float*)d_in[0]; // [256,182,2000]
    const float* W     = (const float*)d_in[1]; // [2,182]
    const float* bias  = (const float*)d_in[2]; // [2]
    const float* alpha = (const float*)d_in[3]; // [2]
    const float* beta  = (const float*)d_in[4]; // [2]
    float* out = (float*)d_out;                 // [256,2000,2]

    snn_fused_kernel<<<GRID, 256>>>(inp, W, bias, alpha, beta, out);
}